// round 13
// baseline (speedup 1.0000x reference)
#include <cuda_runtime.h>
#include <mma.h>
#include <cstdint>

using namespace nvcuda;

#define Bb 2
#define Cc 66
#define Tt 32
#define Nn 512
#define TNc (Tt*Nn)          // 16384
#define BTNc (Bb*TNc)        // 32768
#define Ll 2
#define Kn 16

// ---------------- device scratch (no cudaMalloc allowed) ----------------
static __device__ float g_proj[33554432];     // [BTN][1024]  (134 MB)
static __device__ int   g_nid[BTNc * Kn];     // neighbor global point ids
static __device__ float g_wtf_hi[65536];      // [1024 rows][64 k]  tf32 hi
static __device__ float g_wtf_lo[65536];      // [1024 rows][64 k]  tf32 lo
static __device__ float g_bias[1024];
static __device__ float g_wpos[2 * 256 * 4];  // [l][row(252 pad 256)][4]

// Per-point row layout (stride 1024):
//   l*512 + 0   ..127 : center q|k (+bias)     l*512+128..251 : center v (+bias)
//   l*512 + 256 ..383 : neighbor q|k           l*512+384..507 : neighbor v

__device__ __forceinline__ float to_tf32(float v) {
    unsigned u;
    asm("cvt.rna.tf32.f32 %0, %1;" : "=r"(u) : "f"(v));
    return __uint_as_float(u);
}

// ---------------- K0: weight prep ----------------
__global__ __launch_bounds__(256) void prep_kernel(
        const float* __restrict__ Wqk, const float* __restrict__ bqk,
        const float* __restrict__ Wv,  const float* __restrict__ bv) {
    int i = blockIdx.x * blockDim.x + threadIdx.x;   // 0 .. 65535
    {
        int r = i >> 6, c = i & 63;
        int l = r >> 9, within = r & 511, typ = within >> 8, o = within & 255;
        float w = 0.f;
        if (o < 252 && c < 62) {
            int col = (typ == 0 ? 4 : 66) + c;
            if (o < 128) w = Wqk[(l * 128 + o) * 128 + col];
            else         w = Wv[(l * 124 + (o - 128)) * 128 + col];
        }
        float hi = to_tf32(w);
        float lo = to_tf32(w - hi);
        g_wtf_hi[r * 64 + c] = hi;
        g_wtf_lo[r * 64 + c] = lo;
    }
    if (i < 1024) {
        int r = i, l = r >> 9, within = r & 511, typ = within >> 8, o = within & 255;
        float bb = 0.f;
        if (typ == 0 && o < 252) bb = (o < 128) ? bqk[l * 128 + o] : bv[l * 124 + (o - 128)];
        g_bias[r] = bb;
    }
    if (i < 2048) {
        int l = i >> 10, rem = i & 1023, o = rem >> 2, j = rem & 3;
        float w = 0.f;
        if (o < 128)      w = Wqk[(l * 128 + o) * 128 + j];
        else if (o < 252) w = Wv[(l * 124 + (o - 128)) * 128 + j];
        g_wpos[i] = w;
    }
}

// ---------------- K1: kNN v3 (warp-per-point, lane-distributed sorted top-16) ----------------
__global__ __launch_bounds__(256) void knn_kernel(const float* __restrict__ x) {
    int blk = blockIdx.x;            // 0..4095
    int bt = blk >> 6, seg = blk & 63;
    int b = bt / Tt, t = bt % Tt;
    int tid = threadIdx.x, wid = tid >> 5, lane = tid & 31;
    int n = seg * 8 + wid;

    __shared__ __align__(16) float4 pool[1536];   // 24 KB
    const float* xb = x + (size_t)b * Cc * TNc;
    for (int idx = tid; idx < 1536; idx += 256) {
        int s = idx >> 9, j = idx & 511;
        int tp = t - 1 + s; tp = tp < 0 ? 0 : (tp > Tt - 1 ? Tt - 1 : tp);
        float cx = xb[0 * TNc + tp * Nn + j];
        float cy = xb[1 * TNc + tp * Nn + j];
        float cz = xb[2 * TNc + tp * Nn + j];
        float cc = fmaf(cx, cx, fmaf(cy, cy, cz * cz));
        pool[idx] = make_float4(cx, cy, cz, cc);
    }
    __syncthreads();

    float px = xb[0 * TNc + t * Nn + n];
    float py = xb[1 * TNc + t * Nn + n];
    float pz = xb[2 * TNc + t * Nn + n];

    unsigned long long S = ~0ull;
    unsigned long long thresh = ~0ull;   // 16th best (lane 15's S)

    for (int c0 = 0; c0 < 1536; c0 += 32) {
        int j = c0 + lane;
        float4 cd = pool[j];
        float e = fmaf(-2.f, fmaf(px, cd.x, fmaf(py, cd.y, pz * cd.z)), cd.w);
        unsigned bits = __float_as_uint(e);
        unsigned u = bits ^ ((unsigned)((int)bits >> 31) | 0x80000000u);
        unsigned long long kk = ((unsigned long long)u << 32) | (unsigned)j;

        unsigned mask = __ballot_sync(0xFFFFFFFFu, kk < thresh);
        while (mask) {
            int src = __ffs(mask) - 1;          // ascending j => exact tie order
            mask &= mask - 1;
            unsigned long long val = __shfl_sync(0xFFFFFFFFu, kk, src);
            if (val < thresh) {
                unsigned long long up = __shfl_up_sync(0xFFFFFFFFu, S, 1);
                if (lane < 16 && val < S)
                    S = (lane > 0 && val < up) ? up : val;
                thresh = __shfl_sync(0xFFFFFFFFu, S, 15);
            }
        }
    }

    if (lane < 16) {
        unsigned pj = (unsigned)(S & 0xFFFFFFFFu);
        int s = (int)(pj >> 9), jn = (int)(pj & 511u);
        int tp = t - 1 + s; tp = tp < 0 ? 0 : (tp > Tt - 1 ? Tt - 1 : tp);
        g_nid[(bt * Nn + n) * Kn + lane] = (b * Tt + tp) * Nn + jn;
    }
}

// ---------------- K2: projection GEMM via tf32 tensor cores (3-pass split) ----------------
#define PROJ_SM_FLOATS (8192 + 8192 + 2048 + 1024)
#define PROJ_SM_BYTES  (PROJ_SM_FLOATS * 4)

__global__ __launch_bounds__(256) void proj_kernel(const float* __restrict__ x) {
    extern __shared__ __align__(32) float psm[];
    float* Xhi   = psm;
    float* Xlo   = psm + 8192;
    float* Cst   = psm + 16384;          // [8 warps][256]
    float* biasS = psm + 18432;          // [1024]

    int tid = threadIdx.x, wid = tid >> 5, lane = tid & 31;
    int p0 = blockIdx.x * 128;
    int b = p0 / TNc, rem0 = p0 % TNc;
    const float* xb = x + ((size_t)b * Cc + 4) * TNc + rem0;

    for (int i = tid; i < 8192; i += 256) {
        int c = i >> 7, pt = i & 127;
        float v = (c < 62) ? xb[(size_t)c * TNc + pt] : 0.f;
        float hi = to_tf32(v);
        Xhi[i] = hi;
        Xlo[i] = to_tf32(v - hi);
    }
    for (int i = tid; i < 1024; i += 256) biasS[i] = g_bias[i];
    __syncthreads();

    float* myC = Cst + wid * 256;
    int pt = lane >> 1, rb = (lane & 1) * 8;

    for (int round = 0; round < 8; round++) {
        int rt = round * 8 + wid;
        wmma::fragment<wmma::matrix_a, 16, 16, 8, wmma::precision::tf32, wmma::row_major> Ahi[8], Alo[8];
#pragma unroll
        for (int k8 = 0; k8 < 8; k8++) {
            wmma::load_matrix_sync(Ahi[k8], g_wtf_hi + rt * 1024 + k8 * 8, 64);
            wmma::load_matrix_sync(Alo[k8], g_wtf_lo + rt * 1024 + k8 * 8, 64);
        }
#pragma unroll
        for (int ct = 0; ct < 8; ct++) {
            wmma::fragment<wmma::accumulator, 16, 16, 8, float> C;
            wmma::fill_fragment(C, 0.f);
#pragma unroll
            for (int k8 = 0; k8 < 8; k8++) {
                wmma::fragment<wmma::matrix_b, 16, 16, 8, wmma::precision::tf32, wmma::row_major> Bhi, Blo;
                wmma::load_matrix_sync(Bhi, Xhi + k8 * 8 * 128 + ct * 16, 128);
                wmma::load_matrix_sync(Blo, Xlo + k8 * 8 * 128 + ct * 16, 128);
                wmma::mma_sync(C, Ahi[k8], Bhi, C);
                wmma::mma_sync(C, Ahi[k8], Blo, C);
                wmma::mma_sync(C, Alo[k8], Bhi, C);
            }
            wmma::store_matrix_sync(myC, C, 16, wmma::mem_row_major);
            __syncwarp();
            int rowbase = rt * 16 + rb;
            float vals[8];
#pragma unroll
            for (int ri = 0; ri < 8; ri++)
                vals[ri] = myC[(rb + ri) * 16 + pt] + biasS[rowbase + ri];
            float* dst = g_proj + (size_t)(p0 + ct * 16 + pt) * 1024 + rowbase;
            *(float4*)dst       = make_float4(vals[0], vals[1], vals[2], vals[3]);
            *(float4*)(dst + 4) = make_float4(vals[4], vals[5], vals[6], vals[7]);
            __syncwarp();
        }
    }
}

// ---------------- K3: attention v7 (wmma tf32 energy) ----------------
// per-group floats: qk_hi[16*136]=2176 | qk_lo=2176 | eS[16*20]=320 |
//                   delta8[8][16]f4=512 | nid8=128  -> 5312
#define GSTR 5312
#define AOFF_LO   2176
#define AOFF_ES   4352
#define AOFF_DEL  4672
#define AOFF_NID  5184
#define ATTN_SM_FLOATS (2 * GSTR + 2048 + 2048)
#define ATTN_SM_BYTES  (ATTN_SM_FLOATS * 4)

__device__ __forceinline__ void bar_group(int gi) {
    asm volatile("bar.sync %0, 128;" :: "r"(gi + 1) : "memory");
}

__global__ __launch_bounds__(256, 3) void attn_kernel(const float* __restrict__ x,
                                                      float* __restrict__ out) {
    extern __shared__ __align__(16) float sm[];
    int tid = threadIdx.x;
    int gi = tid >> 7, gt = tid & 127;
    int lane = gt & 31;

    float*  qk_hi   = sm + gi * GSTR;
    float*  qk_lo   = sm + gi * GSTR + AOFF_LO;
    float*  eS      = sm + gi * GSTR + AOFF_ES;       // [16][20] raw energies
    float4* delta8  = (float4*)(sm + gi * GSTR + AOFF_DEL);
    int*    nid8    = (int*)(sm + gi * GSTR + AOFF_NID);
    float*  wposS   = sm + 2 * GSTR;
    float*  outS    = sm + 2 * GSTR + 2048;           // [16][128]

    int p0 = blockIdx.x * 16;
    int b = p0 / TNc, rem0 = p0 % TNc;

    for (int i = tid; i < 2048; i += 256) wposS[i] = g_wpos[i];
    {
        int it = gt >> 4, i = gt & 15;
        int pt = gi * 8 + it;
        int p = p0 + pt;
        int gg = g_nid[p * Kn + i];
        nid8[it * 16 + i] = gg;
        int grem = gg - b * TNc;
        float4 d;
        d.x = x[((size_t)b * Cc + 0) * TNc + rem0 + pt] - x[((size_t)b * Cc + 0) * TNc + grem];
        d.y = x[((size_t)b * Cc + 1) * TNc + rem0 + pt] - x[((size_t)b * Cc + 1) * TNc + grem];
        d.z = x[((size_t)b * Cc + 2) * TNc + rem0 + pt] - x[((size_t)b * Cc + 2) * TNc + grem];
        d.w = x[((size_t)b * Cc + 3) * TNc + rem0 + pt] - x[((size_t)b * Cc + 3) * TNc + grem];
        delta8[it * 16 + i] = d;
    }
    if (tid < 64) {
        int pt = tid >> 2, cc = tid & 3;
        outS[pt * 128 + cc] = x[((size_t)b * Cc + cc) * TNc + rem0 + pt];
    }
    __syncthreads();

    int cch = gt < 124 ? gt : 0;

    for (int l = 0; l < Ll; l++) {
        for (int it = 0; it < 8; it++) {
            int pt = gi * 8 + it;
            int p = p0 + pt;
            const float*  rowC   = g_proj + (size_t)p * 1024 + l * 512;
            const int*    nidS   = nid8 + it * 16;
            const float4* deltaS = delta8 + it * 16;

            // ph1: assemble q,k, split to tf32 hi/lo. thread = channel c = gt
            {
                float4 w4 = *(const float4*)&wposS[l * 1024 + gt * 4];
                float base = rowC[gt];
#pragma unroll
                for (int i = 0; i < 16; i++) {
                    float4 dd = deltaS[i];
                    float nbv = __ldg(&g_proj[(size_t)nidS[i] * 1024 + l * 512 + 256 + gt]);
                    float val = nbv + base + w4.x * dd.x + w4.y * dd.y
                                + w4.z * dd.z + w4.w * dd.w;
                    float hi = to_tf32(val);
                    qk_hi[i * 136 + gt] = hi;
                    qk_lo[i * 136 + gt] = to_tf32(val - hi);
                }
            }
            bar_group(gi);

            // ph2: v-prefetch (all warps) + wmma energy (warp 0 of group)
            float vreg[16];
#pragma unroll
            for (int i = 0; i < 16; i++)
                vreg[i] = __ldg(&g_proj[(size_t)nidS[i] * 1024 + l * 512 + 384 + cch]);

            if (gt < 32) {
                wmma::fragment<wmma::accumulator, 16, 16, 8, float> Chh, Chl, Clh;
                wmma::fill_fragment(Chh, 0.f);
                wmma::fill_fragment(Chl, 0.f);
                wmma::fill_fragment(Clh, 0.f);
#pragma unroll
                for (int k8 = 0; k8 < 8; k8++) {
                    wmma::fragment<wmma::matrix_a, 16, 16, 8, wmma::precision::tf32, wmma::row_major> Ahi, Alo;
                    wmma::fragment<wmma::matrix_b, 16, 16, 8, wmma::precision::tf32, wmma::col_major> Bhi, Blo;
                    wmma::load_matrix_sync(Ahi, qk_hi + k8 * 8, 136);
                    wmma::load_matrix_sync(Alo, qk_lo + k8 * 8, 136);
                    wmma::load_matrix_sync(Bhi, qk_hi + 64 + k8 * 8, 136);
                    wmma::load_matrix_sync(Blo, qk_lo + 64 + k8 * 8, 136);
                    wmma::mma_sync(Chh, Ahi, Bhi, Chh);
                    wmma::mma_sync(Chl, Ahi, Blo, Chl);
                    wmma::mma_sync(Clh, Alo, Bhi, Clh);
                }
#pragma unroll
                for (int r = 0; r < Chh.num_elements; r++)
                    Chh.x[r] += Chl.x[r] + Clh.x[r];
                wmma::store_matrix_sync(eS, Chh, 20, wmma::mem_row_major);
            }
            bar_group(gi);

            // ph3+4: in-warp softmax (scale folded into exp) + out
            {
                float af = 0.f;
                float4 dd = make_float4(0.f, 0.f, 0.f, 0.f);
                if (lane < 16) {
                    const float* er = eS + lane * 20;   // raw (unscaled) energies
                    float m = -1e30f;
#pragma unroll
                    for (int j = 0; j < 16; j++) m = fmaxf(m, er[j]);
                    float sum = 0.f;
#pragma unroll
                    for (int j = 0; j < 16; j++) sum += __expf((er[j] - m) * 0.125f);
                    af = __expf((er[0] - m) * 0.125f) / sum;
                    dd = deltaS[lane];
                }
                float s0 = af, dx = af * dd.x, dy = af * dd.y, dz = af * dd.z, dw = af * dd.w;
#pragma unroll
                for (int off = 16; off > 0; off >>= 1) {
                    s0 += __shfl_xor_sync(0xFFFFFFFFu, s0, off);
                    dx += __shfl_xor_sync(0xFFFFFFFFu, dx, off);
                    dy += __shfl_xor_sync(0xFFFFFFFFu, dy, off);
                    dz += __shfl_xor_sync(0xFFFFFFFFu, dz, off);
                    dw += __shfl_xor_sync(0xFFFFFFFFu, dw, off);
                }
                float4 wv = *(const float4*)&wposS[l * 1024 + (128 + cch) * 4];
                float acc = s0 * rowC[128 + cch]
                          + wv.x * dx + wv.y * dy + wv.z * dz + wv.w * dw;
#pragma unroll
                for (int i = 0; i < 16; i++) {
                    float afi = __shfl_sync(0xFFFFFFFFu, af, i);
                    acc = fmaf(afi, vreg[i], acc);
                }
                if (gt < 124) outS[pt * 128 + 4 + gt] = acc;
            }
            bar_group(gi);   // WAR guard on qk/eS before next assemble
        }
        __syncthreads();
        for (int idx = tid; idx < 2048; idx += 256) {
            int c = idx >> 4, pt = idx & 15;
            out[((size_t)(l * Bb + b) * 128 + c) * TNc + rem0 + pt] = outS[pt * 128 + c];
        }
        __syncthreads();
    }
}

// ---------------- launch ----------------
extern "C" void kernel_launch(void* const* d_in, const int* in_sizes, int n_in,
                              void* d_out, int out_size) {
    const float* x   = (const float*)d_in[0];
    const float* Wqk = (const float*)d_in[1];
    const float* bqk = (const float*)d_in[2];
    const float* Wv  = (const float*)d_in[3];
    const float* bv  = (const float*)d_in[4];
    float* out = (float*)d_out;

    cudaFuncSetAttribute(proj_kernel, cudaFuncAttributeMaxDynamicSharedMemorySize, PROJ_SM_BYTES);
    cudaFuncSetAttribute(attn_kernel, cudaFuncAttributeMaxDynamicSharedMemorySize, ATTN_SM_BYTES);

    prep_kernel<<<256, 256>>>(Wqk, bqk, Wv, bv);
    knn_kernel<<<4096, 256>>>(x);
    proj_kernel<<<BTNc / 128, 256, PROJ_SM_BYTES>>>(x);
    attn_kernel<<<BTNc / 16, 256, ATTN_SM_BYTES>>>(x, out);
}

// round 16
// speedup vs baseline: 1.2489x; 1.2489x over previous
#include <cuda_runtime.h>
#include <mma.h>
#include <cstdint>

using namespace nvcuda;

#define Bb 2
#define Cc 66
#define Tt 32
#define Nn 512
#define TNc (Tt*Nn)          // 16384
#define BTNc (Bb*TNc)        // 32768
#define Ll 2
#define Kn 16

// ---------------- device scratch (no cudaMalloc allowed) ----------------
static __device__ float g_proj[33554432];     // [BTN][1024]  (134 MB)
static __device__ int   g_nid[BTNc * Kn];     // neighbor global point ids
static __device__ float g_wtf_hi[65536];      // [1024 rows][64 k]  tf32 hi
static __device__ float g_wtf_lo[65536];      // [1024 rows][64 k]  tf32 lo
static __device__ float g_bias[1024];
static __device__ float g_wpos[2 * 256 * 4];  // [l][row(252 pad 256)][4]

// Per-point row layout (stride 1024):
//   l*512 + 0   ..127 : center q|k (+bias)     l*512+128..251 : center v (+bias)
//   l*512 + 256 ..383 : neighbor q|k           l*512+384..507 : neighbor v

__device__ __forceinline__ float to_tf32(float v) {
    unsigned u;
    asm("cvt.rna.tf32.f32 %0, %1;" : "=r"(u) : "f"(v));
    return __uint_as_float(u);
}

// ---------------- K0: weight prep ----------------
__global__ __launch_bounds__(256) void prep_kernel(
        const float* __restrict__ Wqk, const float* __restrict__ bqk,
        const float* __restrict__ Wv,  const float* __restrict__ bv) {
    int i = blockIdx.x * blockDim.x + threadIdx.x;   // 0 .. 65535
    {
        int r = i >> 6, c = i & 63;
        int l = r >> 9, within = r & 511, typ = within >> 8, o = within & 255;
        float w = 0.f;
        if (o < 252 && c < 62) {
            int col = (typ == 0 ? 4 : 66) + c;
            if (o < 128) w = Wqk[(l * 128 + o) * 128 + col];
            else         w = Wv[(l * 124 + (o - 128)) * 128 + col];
        }
        float hi = to_tf32(w);
        float lo = to_tf32(w - hi);
        g_wtf_hi[r * 64 + c] = hi;
        g_wtf_lo[r * 64 + c] = lo;
    }
    if (i < 1024) {
        int r = i, l = r >> 9, within = r & 511, typ = within >> 8, o = within & 255;
        float bb = 0.f;
        if (typ == 0 && o < 252) bb = (o < 128) ? bqk[l * 128 + o] : bv[l * 124 + (o - 128)];
        g_bias[r] = bb;
    }
    if (i < 2048) {
        int l = i >> 10, rem = i & 1023, o = rem >> 2, j = rem & 3;
        float w = 0.f;
        if (o < 128)      w = Wqk[(l * 128 + o) * 128 + j];
        else if (o < 252) w = Wv[(l * 124 + (o - 128)) * 128 + j];
        g_wpos[i] = w;
    }
}

// ---------------- K1: kNN v3 (warp-per-point, lane-distributed sorted top-16) ----------------
__global__ __launch_bounds__(256) void knn_kernel(const float* __restrict__ x) {
    int blk = blockIdx.x;            // 0..4095
    int bt = blk >> 6, seg = blk & 63;
    int b = bt / Tt, t = bt % Tt;
    int tid = threadIdx.x, wid = tid >> 5, lane = tid & 31;
    int n = seg * 8 + wid;

    __shared__ __align__(16) float4 pool[1536];   // 24 KB
    const float* xb = x + (size_t)b * Cc * TNc;
    for (int idx = tid; idx < 1536; idx += 256) {
        int s = idx >> 9, j = idx & 511;
        int tp = t - 1 + s; tp = tp < 0 ? 0 : (tp > Tt - 1 ? Tt - 1 : tp);
        float cx = xb[0 * TNc + tp * Nn + j];
        float cy = xb[1 * TNc + tp * Nn + j];
        float cz = xb[2 * TNc + tp * Nn + j];
        float cc = fmaf(cx, cx, fmaf(cy, cy, cz * cz));
        pool[idx] = make_float4(cx, cy, cz, cc);
    }
    __syncthreads();

    float px = xb[0 * TNc + t * Nn + n];
    float py = xb[1 * TNc + t * Nn + n];
    float pz = xb[2 * TNc + t * Nn + n];

    unsigned long long S = ~0ull;
    unsigned long long thresh = ~0ull;   // 16th best (lane 15's S)

    for (int c0 = 0; c0 < 1536; c0 += 32) {
        int j = c0 + lane;
        float4 cd = pool[j];
        float e = fmaf(-2.f, fmaf(px, cd.x, fmaf(py, cd.y, pz * cd.z)), cd.w);
        unsigned bits = __float_as_uint(e);
        unsigned u = bits ^ ((unsigned)((int)bits >> 31) | 0x80000000u);
        unsigned long long kk = ((unsigned long long)u << 32) | (unsigned)j;

        unsigned mask = __ballot_sync(0xFFFFFFFFu, kk < thresh);
        while (mask) {
            int src = __ffs(mask) - 1;          // ascending j => exact tie order
            mask &= mask - 1;
            unsigned long long val = __shfl_sync(0xFFFFFFFFu, kk, src);
            if (val < thresh) {
                unsigned long long up = __shfl_up_sync(0xFFFFFFFFu, S, 1);
                if (lane < 16 && val < S)
                    S = (lane > 0 && val < up) ? up : val;
                thresh = __shfl_sync(0xFFFFFFFFu, S, 15);
            }
        }
    }

    if (lane < 16) {
        unsigned pj = (unsigned)(S & 0xFFFFFFFFu);
        int s = (int)(pj >> 9), jn = (int)(pj & 511u);
        int tp = t - 1 + s; tp = tp < 0 ? 0 : (tp > Tt - 1 ? Tt - 1 : tp);
        g_nid[(bt * Nn + n) * Kn + lane] = (b * Tt + tp) * Nn + jn;
    }
}

// ---------------- K2: projection GEMM via tf32 tensor cores (3-pass split) ----------------
#define PROJ_SM_FLOATS (8192 + 8192 + 2048 + 1024)
#define PROJ_SM_BYTES  (PROJ_SM_FLOATS * 4)

__global__ __launch_bounds__(256) void proj_kernel(const float* __restrict__ x) {
    extern __shared__ __align__(32) float psm[];
    float* Xhi   = psm;
    float* Xlo   = psm + 8192;
    float* Cst   = psm + 16384;          // [8 warps][256]
    float* biasS = psm + 18432;          // [1024]

    int tid = threadIdx.x, wid = tid >> 5, lane = tid & 31;
    int p0 = blockIdx.x * 128;
    int b = p0 / TNc, rem0 = p0 % TNc;
    const float* xb = x + ((size_t)b * Cc + 4) * TNc + rem0;

    for (int i = tid; i < 8192; i += 256) {
        int c = i >> 7, pt = i & 127;
        float v = (c < 62) ? xb[(size_t)c * TNc + pt] : 0.f;
        float hi = to_tf32(v);
        Xhi[i] = hi;
        Xlo[i] = to_tf32(v - hi);
    }
    for (int i = tid; i < 1024; i += 256) biasS[i] = g_bias[i];
    __syncthreads();

    float* myC = Cst + wid * 256;
    int pt = lane >> 1, rb = (lane & 1) * 8;

    for (int round = 0; round < 8; round++) {
        int rt = round * 8 + wid;
        wmma::fragment<wmma::matrix_a, 16, 16, 8, wmma::precision::tf32, wmma::row_major> Ahi[8], Alo[8];
#pragma unroll
        for (int k8 = 0; k8 < 8; k8++) {
            wmma::load_matrix_sync(Ahi[k8], g_wtf_hi + rt * 1024 + k8 * 8, 64);
            wmma::load_matrix_sync(Alo[k8], g_wtf_lo + rt * 1024 + k8 * 8, 64);
        }
#pragma unroll
        for (int ct = 0; ct < 8; ct++) {
            wmma::fragment<wmma::accumulator, 16, 16, 8, float> C;
            wmma::fill_fragment(C, 0.f);
#pragma unroll
            for (int k8 = 0; k8 < 8; k8++) {
                wmma::fragment<wmma::matrix_b, 16, 16, 8, wmma::precision::tf32, wmma::row_major> Bhi, Blo;
                wmma::load_matrix_sync(Bhi, Xhi + k8 * 8 * 128 + ct * 16, 128);
                wmma::load_matrix_sync(Blo, Xlo + k8 * 8 * 128 + ct * 16, 128);
                wmma::mma_sync(C, Ahi[k8], Bhi, C);
                wmma::mma_sync(C, Ahi[k8], Blo, C);
                wmma::mma_sync(C, Alo[k8], Bhi, C);
            }
            wmma::store_matrix_sync(myC, C, 16, wmma::mem_row_major);
            __syncwarp();
            int rowbase = rt * 16 + rb;
            float vals[8];
#pragma unroll
            for (int ri = 0; ri < 8; ri++)
                vals[ri] = myC[(rb + ri) * 16 + pt] + biasS[rowbase + ri];
            float* dst = g_proj + (size_t)(p0 + ct * 16 + pt) * 1024 + rowbase;
            *(float4*)dst       = make_float4(vals[0], vals[1], vals[2], vals[3]);
            *(float4*)(dst + 4) = make_float4(vals[4], vals[5], vals[6], vals[7]);
            __syncwarp();
        }
    }
}

// ---------------- K3: attention v5 (R12 build + outS stride 130 anti-conflict pad) ----------------
#define GSTR 3040
#define OSTR 130
#define SM_FLOATS (2 * GSTR + 2048 + 16 * OSTR)

__device__ __forceinline__ void bar_group(int gi) {
    asm volatile("bar.sync %0, 128;" :: "r"(gi + 1) : "memory");
}

__global__ __launch_bounds__(256, 4) void attn_kernel(const float* __restrict__ x,
                                                      float* __restrict__ out) {
    __shared__ __align__(16) float sm[SM_FLOATS];
    int tid = threadIdx.x;
    int gi = tid >> 7, gt = tid & 127;
    int lane = gt & 31;

    float*  qk      = sm + gi * GSTR;                  // [16][132]
    float*  eS      = sm + gi * GSTR + 2112;           // [16][17]
    float4* delta8  = (float4*)(sm + gi * GSTR + 2384); // [8 pts][16]
    int*    nid8    = (int*)(sm + gi * GSTR + 2896);    // [8 pts][16]
    float*  wposS   = sm + 2 * GSTR;
    float*  outS    = sm + 2 * GSTR + 2048;            // [16][OSTR] (one layer)

    int p0 = blockIdx.x * 16;
    int b = p0 / TNc, rem0 = p0 % TNc;

    for (int i = tid; i < 2048; i += 256) wposS[i] = g_wpos[i];
    {
        int it = gt >> 4, i = gt & 15;
        int pt = gi * 8 + it;
        int p = p0 + pt;
        int gg = g_nid[p * Kn + i];
        nid8[it * 16 + i] = gg;
        int grem = gg - b * TNc;
        float4 d;
        d.x = x[((size_t)b * Cc + 0) * TNc + rem0 + pt] - x[((size_t)b * Cc + 0) * TNc + grem];
        d.y = x[((size_t)b * Cc + 1) * TNc + rem0 + pt] - x[((size_t)b * Cc + 1) * TNc + grem];
        d.z = x[((size_t)b * Cc + 2) * TNc + rem0 + pt] - x[((size_t)b * Cc + 2) * TNc + grem];
        d.w = x[((size_t)b * Cc + 3) * TNc + rem0 + pt] - x[((size_t)b * Cc + 3) * TNc + grem];
        delta8[it * 16 + i] = d;
    }
    if (tid < 64) {
        int pt = tid >> 2, cc = tid & 3;
        outS[pt * OSTR + cc] = x[((size_t)b * Cc + cc) * TNc + rem0 + pt];
    }
    __syncthreads();

    int cch = gt < 124 ? gt : 0;   // clamped v-channel for tail lanes

    for (int l = 0; l < Ll; l++) {
        for (int it = 0; it < 8; it++) {
            int pt = gi * 8 + it;
            int p = p0 + pt;
            const float*  rowC   = g_proj + (size_t)p * 1024 + l * 512;
            const int*    nidS   = nid8 + it * 16;
            const float4* deltaS = delta8 + it * 16;

            // ph1: assemble q,k (i-major). thread = channel c = gt
            {
                float4 w4 = *(const float4*)&wposS[l * 1024 + gt * 4];
                float base = rowC[gt];
#pragma unroll
                for (int i = 0; i < 16; i++) {
                    float4 dd = deltaS[i];
                    float nbv = __ldg(&g_proj[(size_t)nidS[i] * 1024 + l * 512 + 256 + gt]);
                    qk[i * 132 + gt] = nbv + base + w4.x * dd.x + w4.y * dd.y
                                       + w4.z * dd.z + w4.w * dd.w;
                }
            }
            bar_group(gi);

            // ph2: prefetch v-gather into regs, then energy
            float vreg[16];
            {
#pragma unroll
                for (int i = 0; i < 16; i++)
                    vreg[i] = __ldg(&g_proj[(size_t)nidS[i] * 1024 + l * 512 + 384 + cch]);

                int i = gt >> 3, jh = gt & 7;
                const float* qb = qk + i * 132;
                const float* k0 = qk + jh * 132 + 64;
                const float* k1 = qk + (jh + 8) * 132 + 64;
                float a0 = 0.f, a1 = 0.f;
#pragma unroll
                for (int c4 = 0; c4 < 16; c4++) {
                    float4 q4 = *(const float4*)(qb + c4 * 4);
                    float4 ka = *(const float4*)(k0 + c4 * 4);
                    float4 kb = *(const float4*)(k1 + c4 * 4);
                    a0 = fmaf(q4.x, ka.x, a0); a0 = fmaf(q4.y, ka.y, a0);
                    a0 = fmaf(q4.z, ka.z, a0); a0 = fmaf(q4.w, ka.w, a0);
                    a1 = fmaf(q4.x, kb.x, a1); a1 = fmaf(q4.y, kb.y, a1);
                    a1 = fmaf(q4.z, kb.z, a1); a1 = fmaf(q4.w, kb.w, a1);
                }
                eS[i * 17 + jh] = a0 * 0.125f;
                eS[i * 17 + jh + 8] = a1 * 0.125f;
            }
            bar_group(gi);

            // ph3+4: in-warp redundant softmax + out
            {
                float af = 0.f;
                float4 dd = make_float4(0.f, 0.f, 0.f, 0.f);
                if (lane < 16) {
                    const float* er = eS + lane * 17;
                    float m = -1e30f;
#pragma unroll
                    for (int j = 0; j < 16; j++) m = fmaxf(m, er[j]);
                    float sum = 0.f;
#pragma unroll
                    for (int j = 0; j < 16; j++) sum += __expf(er[j] - m);
                    af = __expf(er[0] - m) / sum;
                    dd = deltaS[lane];
                }
                float s0 = af, dx = af * dd.x, dy = af * dd.y, dz = af * dd.z, dw = af * dd.w;
#pragma unroll
                for (int off = 16; off > 0; off >>= 1) {
                    s0 += __shfl_xor_sync(0xFFFFFFFFu, s0, off);
                    dx += __shfl_xor_sync(0xFFFFFFFFu, dx, off);
                    dy += __shfl_xor_sync(0xFFFFFFFFu, dy, off);
                    dz += __shfl_xor_sync(0xFFFFFFFFu, dz, off);
                    dw += __shfl_xor_sync(0xFFFFFFFFu, dw, off);
                }
                float4 wv = *(const float4*)&wposS[l * 1024 + (128 + cch) * 4];
                float acc = s0 * rowC[128 + cch]
                          + wv.x * dx + wv.y * dy + wv.z * dz + wv.w * dw;
#pragma unroll
                for (int i = 0; i < 16; i++) {
                    float afi = __shfl_sync(0xFFFFFFFFu, af, i);
                    acc = fmaf(afi, vreg[i], acc);
                }
                if (gt < 124) outS[pt * OSTR + 4 + gt] = acc;
            }
            bar_group(gi);   // WAR guard on qk/eS before next assemble
        }
        __syncthreads();
        for (int idx = tid; idx < 2048; idx += 256) {
            int c = idx >> 4, pt = idx & 15;
            out[((size_t)(l * Bb + b) * 128 + c) * TNc + rem0 + pt] = outS[pt * OSTR + c];
        }
        __syncthreads();
    }
}

// ---------------- launch ----------------
extern "C" void kernel_launch(void* const* d_in, const int* in_sizes, int n_in,
                              void* d_out, int out_size) {
    const float* x   = (const float*)d_in[0];
    const float* Wqk = (const float*)d_in[1];
    const float* bqk = (const float*)d_in[2];
    const float* Wv  = (const float*)d_in[3];
    const float* bv  = (const float*)d_in[4];
    float* out = (float*)d_out;

    cudaFuncSetAttribute(proj_kernel, cudaFuncAttributeMaxDynamicSharedMemorySize, PROJ_SM_BYTES);

    prep_kernel<<<256, 256>>>(Wqk, bqk, Wv, bv);
    knn_kernel<<<4096, 256>>>(x);
    proj_kernel<<<BTNc / 128, 256, PROJ_SM_BYTES>>>(x);
    attn_kernel<<<BTNc / 16, 256>>>(x, out);
}